// round 14
// baseline (speedup 1.0000x reference)
#include <cuda_runtime.h>
#include <cuda_fp16.h>
#include <math.h>
#include <stdint.h>

#define T_  2048
#define D_  1024
#define I_  512
#define E_  32
#define K_  6
#define SI_ 1024

#define BM 64
#define BN 128
#define BK 32
#define RSTR 20                   // smem row stride in 4B words (16 data + 4 pad), conflict-free
#define AB (BM * RSTR * 4)        // 5120 B per A stage
#define BB (BN * RSTR * 4)        // 10240 B per B stage
#define AWRD (BM * RSTR)          // 1280 words
#define BWRD (BN * RSTR)          // 2560 words

// smem layouts (bytes): dual A[2]@0, B1[2]@10240, B2[2]@30720, slots@51200
//                       single A[2]@0, B[2]@10240, slots@30720
#define DUAL_SMEM   (51200 + 256)
#define SINGLE_SMEM (30720 + 256)

// ---------------- scratch (no allocations allowed) ----------------
__device__ __half g_w1h[E_ * I_ * D_];   // W1^T per expert: [I][D] fp16
__device__ __half g_w2h[E_ * I_ * D_];
__device__ __half g_w3h[E_ * D_ * I_];   // W3^T: [D][I]
__device__ __half g_sw1h[SI_ * D_];      // sw1^T: [SI][D]
__device__ __half g_sw2h[SI_ * D_];
__device__ __half g_sw3h[D_ * SI_];      // sw3^T: [D][SI]
__device__ __half g_xh[T_ * D_];         // x fp16
__device__ __half g_zh[T_ * SI_];        // shared hidden fp16
__device__ __half g_hs[T_ * K_ * I_];    // routed hidden fp16
__device__ int    g_cnt[E_];
__device__ int    g_slots[E_ * T_];
__device__ int    g_tidx[T_ * K_];
__device__ float  g_tval[T_ * K_];

__device__ __forceinline__ void cpa16(unsigned dst, const void* src) {
    asm volatile("cp.async.cg.shared.global [%0], [%1], 16;" :: "r"(dst), "l"(src));
}
#define CP_COMMIT asm volatile("cp.async.commit_group;")
#define CP_WAIT1  asm volatile("cp.async.wait_group 1;")
#define CP_WAIT0  asm volatile("cp.async.wait_group 0;")

#define MMA16(c, a, b0v, b1v) \
    asm volatile("mma.sync.aligned.m16n8k16.row.col.f32.f16.f16.f32 " \
        "{%0,%1,%2,%3},{%4,%5,%6,%7},{%8,%9},{%0,%1,%2,%3};" \
        : "+f"((c)[0]), "+f"((c)[1]), "+f"((c)[2]), "+f"((c)[3]) \
        : "r"((a)[0]), "r"((a)[1]), "r"((a)[2]), "r"((a)[3]), "r"(b0v), "r"(b1v))

// ---------------- init ----------------
__global__ void moe_init_kernel() {
    if (threadIdx.x < E_) g_cnt[threadIdx.x] = 0;
}

// ---------------- transpose + fp16 convert: src f32 [R][C] -> DEVICE-RESOLVED dst fp16 [C][R] ----
// R9/R13 bug: passing __device__ symbols as host-side kernel args yields the host
// shadow address (silently writable via ATS on GB300). Resolve the dst in device code.
__device__ __forceinline__ __half* tr_dst(int which) {
    switch (which) {
        case 0: return g_w1h;
        case 1: return g_w2h;
        case 2: return g_w3h;
        case 3: return g_sw1h;
        case 4: return g_sw2h;
        default: return g_sw3h;
    }
}

__global__ __launch_bounds__(256) void moe_tr_kernel(
    const float* __restrict__ src, int which, int R, int C)
{
    __shared__ float t[32][33];
    __half* dst = tr_dst(which);
    const size_t msz = (size_t)R * C;
    src += blockIdx.z * msz;
    dst += blockIdx.z * msz;
    const int c0 = blockIdx.x * 32, r0 = blockIdx.y * 32;
    const int tx = threadIdx.x, ty = threadIdx.y;
    #pragma unroll
    for (int i = ty; i < 32; i += 8)
        t[i][tx] = src[(size_t)(r0 + i) * C + c0 + tx];
    __syncthreads();
    #pragma unroll
    for (int i = ty; i < 32; i += 8)
        dst[(size_t)(c0 + i) * R + r0 + tx] = __float2half_rn(t[tx][i]);
}

// ---------------- x -> fp16 ----------------
__global__ __launch_bounds__(256) void moe_cvtx_kernel(const float* __restrict__ x) {
    long i = (long)blockIdx.x * 256 + threadIdx.x;
    float4 v = ((const float4*)x)[i];
    ((__half2*)g_xh)[i * 2]     = __floats2half2_rn(v.x, v.y);
    ((__half2*)g_xh)[i * 2 + 1] = __floats2half2_rn(v.z, v.w);
}

// ---------------- router: 1 warp per token (validated, fp32) ----------------
__global__ __launch_bounds__(256) void moe_router_kernel(
    const float* __restrict__ x, const float* __restrict__ rw, const float* __restrict__ rb)
{
    __shared__ float sh[8][32];
    const int wi = threadIdx.x >> 5, lane = threadIdx.x & 31;
    const int t = blockIdx.x * 8 + wi;

    const float4* xr = (const float4*)(x + (size_t)t * D_);
    float4 xv[8];
    #pragma unroll
    for (int d = 0; d < 8; d++) xv[d] = xr[d * 32 + lane];

    for (int e = 0; e < E_; e += 2) {
        const float4* w0 = (const float4*)(rw + (size_t)e * D_);
        const float4* w1 = (const float4*)(rw + (size_t)(e + 1) * D_);
        float acc0 = 0.f, acc1 = 0.f;
        #pragma unroll
        for (int d = 0; d < 8; d++) {
            float4 b0 = w0[d * 32 + lane], b1 = w1[d * 32 + lane];
            acc0 += xv[d].x * b0.x + xv[d].y * b0.y + xv[d].z * b0.z + xv[d].w * b0.w;
            acc1 += xv[d].x * b1.x + xv[d].y * b1.y + xv[d].z * b1.z + xv[d].w * b1.w;
        }
        #pragma unroll
        for (int off = 16; off; off >>= 1) {
            acc0 += __shfl_down_sync(0xffffffffu, acc0, off);
            acc1 += __shfl_down_sync(0xffffffffu, acc1, off);
        }
        if (lane == 0) { sh[wi][e] = acc0 + rb[e]; sh[wi][e + 1] = acc1 + rb[e + 1]; }
    }
    __syncwarp();
    float logit = sh[wi][lane];

    float mx = logit;
    #pragma unroll
    for (int off = 16; off; off >>= 1)
        mx = fmaxf(mx, __shfl_xor_sync(0xffffffffu, mx, off));
    float p = expf(logit - mx);
    float sm = p;
    #pragma unroll
    for (int off = 16; off; off >>= 1)
        sm += __shfl_xor_sync(0xffffffffu, sm, off);
    float score = p / sm;

    const int grp = lane >> 2;
    float v0 = __shfl_sync(0xffffffffu, score, grp * 4 + 0);
    float v1 = __shfl_sync(0xffffffffu, score, grp * 4 + 1);
    float v2 = __shfl_sync(0xffffffffu, score, grp * 4 + 2);
    float v3 = __shfl_sync(0xffffffffu, score, grp * 4 + 3);
    float a = fmaxf(v0, v1), b = fminf(v0, v1);
    float c = fmaxf(v2, v3), dd = fminf(v2, v3);
    float top2 = (a >= c) ? (a + fmaxf(b, c)) : (c + fmaxf(a, dd));

    float gsa[8];
    #pragma unroll
    for (int j = 0; j < 8; j++) gsa[j] = __shfl_sync(0xffffffffu, top2, j * 4);
    unsigned keep = 0;
    #pragma unroll
    for (int it = 0; it < 4; it++) {
        float bv = -1e30f; int bj = 0;
        #pragma unroll
        for (int j = 0; j < 8; j++) {
            bool cand = (((keep >> j) & 1u) == 0u) && (gsa[j] > bv);
            if (cand) { bv = gsa[j]; bj = j; }
        }
        keep |= 1u << bj;
    }

    float msc = ((keep >> grp) & 1u) ? score : -1e30f;
    __syncwarp();
    sh[wi][lane] = msc;
    __syncwarp();

    if (lane == 0) {
        #pragma unroll
        for (int kk = 0; kk < K_; kk++) {
            float bv = -1e30f; int be = 0;
            for (int ee = 0; ee < 32; ee++) {
                float s = sh[wi][ee];
                if (s > bv) { bv = s; be = ee; }
            }
            sh[wi][be] = -2e30f;
            g_tidx[t * K_ + kk] = be;
            g_tval[t * K_ + kk] = bv;
            int pos = atomicAdd(&g_cnt[be], 1);
            g_slots[be * T_ + pos] = t * K_ + kk;
        }
    }
}

// ---------------- bias pre-pass: out[t] = sb3 + sum_k gate_k * b3[e_k] ----------------
__global__ __launch_bounds__(256) void moe_bias_kernel(
    const float* __restrict__ b3, const float* __restrict__ sb3, float* __restrict__ out)
{
    const int t = blockIdx.x;
    int ti[K_]; float tv[K_];
    #pragma unroll
    for (int k = 0; k < K_; k++) { ti[k] = g_tidx[t * K_ + k]; tv[k] = g_tval[t * K_ + k]; }
    for (int n = threadIdx.x * 4; n < D_; n += blockDim.x * 4) {
        float4 v = *(const float4*)(sb3 + n);
        #pragma unroll
        for (int k = 0; k < K_; k++) {
            float4 bb = *(const float4*)(b3 + (size_t)ti[k] * D_ + n);
            v.x = fmaf(tv[k], bb.x, v.x); v.y = fmaf(tv[k], bb.y, v.y);
            v.z = fmaf(tv[k], bb.z, v.z); v.w = fmaf(tv[k], bb.w, v.w);
        }
        *(float4*)(out + (size_t)t * D_ + n) = v;
    }
}

// ======================================================================
// fp16 m16n8k16 GEMMs. R7 skeleton: 256 thr, 8 warps (2x4), warp 32x32,
// BK=32 (2 k16-slices), 2-stage: wait -> sync -> compute -> sync -> prefetch.
// A smem [m][k] fp16, B smem [n][k] fp16 (weights pre-transposed), row = 20 words.
// ======================================================================

#define A_COPY(dstbase, rowptr, k0)  cpa16((dstbase), (rowptr) + (k0) + ac * 8)
#define B_COPY(dstbase, gbase, ldk, k0) do { \
    cpa16((dstbase),      (gbase) + (size_t)bn * (ldk) + (k0) + bh * 16); \
    cpa16((dstbase) + 16, (gbase) + (size_t)bn * (ldk) + (k0) + bh * 16 + 8); \
} while (0)

#define WARP_IDS \
    const int lane = tid & 31, warp = tid >> 5; \
    const int wm = warp >> 2, wn = warp & 3; \
    const int grp = lane >> 2, tq = lane & 3; \
    const int mbase = wm * 32, nbase = wn * 32;

#define LOAD_AFRAGS(Ar) \
    unsigned a0[4], a1[4]; \
    { int r0 = mbase + grp; \
      a0[0] = (Ar)[r0 * RSTR + kq];     a0[1] = (Ar)[(r0 + 8) * RSTR + kq]; \
      a0[2] = (Ar)[r0 * RSTR + kq + 4]; a0[3] = (Ar)[(r0 + 8) * RSTR + kq + 4]; \
      int r1 = r0 + 16; \
      a1[0] = (Ar)[r1 * RSTR + kq];     a1[1] = (Ar)[(r1 + 8) * RSTR + kq]; \
      a1[2] = (Ar)[r1 * RSTR + kq + 4]; a1[3] = (Ar)[(r1 + 8) * RSTR + kq + 4]; }

// ---- shared stage 1 (dual B): g_zh = fp16(silu((x@sw1+sb1)*(x@sw2+sb2))) ----
__global__ __launch_bounds__(256, 2) void moe_shared_h_kernel(
    const float* __restrict__ sb1, const float* __restrict__ sb2)
{
    extern __shared__ __align__(16) char dsm[];
    const unsigned smb = (unsigned)__cvta_generic_to_shared(dsm);
    const int tid = threadIdx.x;
    const int mb = blockIdx.y * BM, nb = blockIdx.x * BN;
    const int am = tid >> 2, ac = tid & 3;
    const int bn = tid >> 1, bh = tid & 1;

    const __half* aRow = g_xh   + (size_t)(mb + am) * D_;
    const __half* B1g  = g_sw1h + (size_t)nb * D_;
    const __half* B2g  = g_sw2h + (size_t)nb * D_;
    const unsigned aD  = smb + am * 80 + ac * 16;
    const unsigned b1D = smb + 10240 + bn * 80 + bh * 32;
    const unsigned b2D = smb + 30720 + bn * 80 + bh * 32;

    WARP_IDS;

    float c1[2][4][4] = {}, c2[2][4][4] = {};

    #pragma unroll
    for (int s = 0; s < 2; s++) {
        A_COPY(aD + s * AB, aRow, s * BK);
        B_COPY(b1D + s * BB, B1g, D_, s * BK);
        B_COPY(b2D + s * BB, B2g, D_, s * BK);
        CP_COMMIT;
    }

    const int NT = D_ / BK;
    #pragma unroll 1
    for (int kt = 0; kt < NT; kt++) {
        const int s = kt & 1;
        if (kt + 1 < NT) CP_WAIT1; else CP_WAIT0;
        __syncthreads();
        const unsigned* Ar  = (const unsigned*)dsm + s * AWRD;
        const unsigned* B1r = (const unsigned*)dsm + 2560 + s * BWRD;
        const unsigned* B2r = (const unsigned*)dsm + 7680 + s * BWRD;
        #pragma unroll
        for (int ks = 0; ks < 2; ks++) {
            const int kq = ks * 8 + tq;
            LOAD_AFRAGS(Ar);
            #pragma unroll
            for (int in = 0; in < 4; in++) {
                int nc = nbase + in * 8 + grp;
                unsigned p0 = B1r[nc * RSTR + kq], p1 = B1r[nc * RSTR + kq + 4];
                unsigned q0 = B2r[nc * RSTR + kq], q1 = B2r[nc * RSTR + kq + 4];
                MMA16(c1[0][in], a0, p0, p1);
                MMA16(c1[1][in], a1, p0, p1);
                MMA16(c2[0][in], a0, q0, q1);
                MMA16(c2[1][in], a1, q0, q1);
            }
        }
        if (kt + 2 < NT) {
            __syncthreads();
            const int k0 = (kt + 2) * BK;
            A_COPY(aD + s * AB, aRow, k0);
            B_COPY(b1D + s * BB, B1g, D_, k0);
            B_COPY(b2D + s * BB, B2g, D_, k0);
            CP_COMMIT;
        }
    }

    #pragma unroll
    for (int im = 0; im < 2; im++)
        #pragma unroll
        for (int in = 0; in < 4; in++)
            #pragma unroll
            for (int h = 0; h < 2; h++) {
                int row = mb + mbase + im * 16 + grp + h * 8;
                int base = nb + nbase + in * 8;
                float r0v, r1v;
                {
                    float h1 = c1[im][in][h * 2]     + sb1[base + 2 * tq];
                    float h2 = c2[im][in][h * 2]     + sb2[base + 2 * tq];
                    float pp = h1 * h2;
                    r0v = pp / (1.f + expf(-pp));
                }
                {
                    float h1 = c1[im][in][h * 2 + 1] + sb1[base + 2 * tq + 1];
                    float h2 = c2[im][in][h * 2 + 1] + sb2[base + 2 * tq + 1];
                    float pp = h1 * h2;
                    r1v = pp / (1.f + expf(-pp));
                }
                *(__half2*)(g_zh + (size_t)row * SI_ + base + 2 * tq) = __floats2half2_rn(r0v, r1v);
            }
}

// ---- shared stage 2: out += g_zh @ sw3 ----
__global__ __launch_bounds__(256, 2) void moe_out_init_kernel(float* __restrict__ out)
{
    extern __shared__ __align__(16) char dsm[];
    const unsigned smb = (unsigned)__cvta_generic_to_shared(dsm);
    const int tid = threadIdx.x;
    const int mb = blockIdx.y * BM, nb = blockIdx.x * BN;
    const int am = tid >> 2, ac = tid & 3;
    const int bn = tid >> 1, bh = tid & 1;

    const __half* aRow = g_zh   + (size_t)(mb + am) * SI_;
    const __half* Bg   = g_sw3h + (size_t)nb * SI_;
    const unsigned aD = smb + am * 80 + ac * 16;
    const unsigned bD = smb + 10240 + bn * 80 + bh * 32;

    WARP_IDS;

    float c[2][4][4] = {};

    #pragma unroll
    for (int s = 0; s < 2; s++) {
        A_COPY(aD + s * AB, aRow, s * BK);
        B_COPY(bD + s * BB, Bg, SI_, s * BK);
        CP_COMMIT;
    }

    const int NT = SI_ / BK;
    #pragma unroll 1
    for (int kt = 0; kt < NT; kt++) {
        const int s = kt & 1;
        if (kt + 1 < NT) CP_WAIT1; else CP_WAIT0;
        __syncthreads();
        const unsigned* Ar = (const unsigned*)dsm + s * AWRD;
        const unsigned* Br = (const unsigned*)dsm + 2560 + s * BWRD;
        #pragma unroll
        for (int ks = 0; ks < 2; ks++) {
            const int kq = ks * 8 + tq;
            LOAD_AFRAGS(Ar);
            #pragma unroll
            for (int in = 0; in < 4; in++) {
                int nc = nbase + in * 8 + grp;
                unsigned p0 = Br[nc * RSTR + kq], p1 = Br[nc * RSTR + kq + 4];
                MMA16(c[0][in], a0, p0, p1);
                MMA16(c[1][in], a1, p0, p1);
            }
        }
        if (kt + 2 < NT) {
            __syncthreads();
            const int k0 = (kt + 2) * BK;
            A_COPY(aD + s * AB, aRow, k0);
            B_COPY(bD + s * BB, Bg, SI_, k0);
            CP_COMMIT;
        }
    }

    #pragma unroll
    for (int im = 0; im < 2; im++)
        #pragma unroll
        for (int in = 0; in < 4; in++)
            #pragma unroll
            for (int r = 0; r < 4; r++) {
                int row = mb + mbase + im * 16 + grp + (r >= 2 ? 8 : 0);
                int col = nb + nbase + in * 8 + 2 * tq + (r & 1);
                out[(size_t)row * D_ + col] += c[im][in][r];
            }
}

// ---- routed stage 1 (dual B, gathered rows) ----
__global__ __launch_bounds__(256, 2) void moe_routed_h_kernel(
    const float* __restrict__ b1, const float* __restrict__ b2)
{
    const int e = blockIdx.z;
    const int cnt = g_cnt[e];
    const int mb = blockIdx.y * BM;
    if (mb >= cnt) return;
    const int nb = blockIdx.x * BN;

    extern __shared__ __align__(16) char dsm[];
    const unsigned smb = (unsigned)__cvta_generic_to_shared(dsm);
    int* slotS = (int*)(dsm + 51200);
    const int tid = threadIdx.x;

    if (tid < BM) {
        int m = mb + tid;
        slotS[tid] = (m < cnt) ? g_slots[e * T_ + m] : g_slots[e * T_];
    }
    __syncthreads();

    const int am = tid >> 2, ac = tid & 3;
    const int bn = tid >> 1, bh = tid & 1;

    const __half* aRow = g_xh + (size_t)(slotS[am] / K_) * D_;
    const __half* B1g  = g_w1h + (size_t)e * I_ * D_ + (size_t)nb * D_;
    const __half* B2g  = g_w2h + (size_t)e * I_ * D_ + (size_t)nb * D_;
    const unsigned aD  = smb + am * 80 + ac * 16;
    const unsigned b1D = smb + 10240 + bn * 80 + bh * 32;
    const unsigned b2D = smb + 30720 + bn * 80 + bh * 32;

    WARP_IDS;

    float c1[2][4][4] = {}, c2[2][4][4] = {};

    #pragma unroll
    for (int s = 0; s < 2; s++) {
        A_COPY(aD + s * AB, aRow, s * BK);
        B_COPY(b1D + s * BB, B1g, D_, s * BK);
        B_COPY(b2D + s * BB, B2g, D_, s * BK);
        CP_COMMIT;
    }

    const int NT = D_ / BK;
    #pragma unroll 1
    for (int kt = 0; kt < NT; kt++) {
        const int s = kt & 1;
        if (kt + 1 < NT) CP_WAIT1; else CP_WAIT0;
        __syncthreads();
        const unsigned* Ar  = (const unsigned*)dsm + s * AWRD;
        const unsigned* B1r = (const unsigned*)dsm + 2560 + s * BWRD;
        const unsigned* B2r = (const unsigned*)dsm + 7680 + s * BWRD;
        #pragma unroll
        for (int ks = 0; ks < 2; ks++) {
            const int kq = ks * 8 + tq;
            LOAD_AFRAGS(Ar);
            #pragma unroll
            for (int in = 0; in < 4; in++) {
                int nc = nbase + in * 8 + grp;
                unsigned p0 = B1r[nc * RSTR + kq], p1 = B1r[nc * RSTR + kq + 4];
                unsigned q0 = B2r[nc * RSTR + kq], q1 = B2r[nc * RSTR + kq + 4];
                MMA16(c1[0][in], a0, p0, p1);
                MMA16(c1[1][in], a1, p0, p1);
                MMA16(c2[0][in], a0, q0, q1);
                MMA16(c2[1][in], a1, q0, q1);
            }
        }
        if (kt + 2 < NT) {
            __syncthreads();
            const int k0 = (kt + 2) * BK;
            A_COPY(aD + s * AB, aRow, k0);
            B_COPY(b1D + s * BB, B1g, D_, k0);
            B_COPY(b2D + s * BB, B2g, D_, k0);
            CP_COMMIT;
        }
    }

    #pragma unroll
    for (int im = 0; im < 2; im++)
        #pragma unroll
        for (int h = 0; h < 2; h++) {
            int lr = mbase + im * 16 + grp + h * 8;
            bool valid = (mb + lr) < cnt;
            int s = slotS[lr];
            float gv = g_tval[s];
            #pragma unroll
            for (int in = 0; in < 4; in++) {
                int base = nb + nbase + in * 8;
                float r0v, r1v;
                {
                    float h1 = c1[im][in][h * 2]     + b1[(size_t)e * I_ + base + 2 * tq];
                    float h2 = c2[im][in][h * 2]     + b2[(size_t)e * I_ + base + 2 * tq];
                    float pp = h1 * h2;
                    r0v = gv * pp / (1.f + expf(-pp));
                }
                {
                    float h1 = c1[im][in][h * 2 + 1] + b1[(size_t)e * I_ + base + 2 * tq + 1];
                    float h2 = c2[im][in][h * 2 + 1] + b2[(size_t)e * I_ + base + 2 * tq + 1];
                    float pp = h1 * h2;
                    r1v = gv * pp / (1.f + expf(-pp));
                }
                if (valid)
                    *(__half2*)(g_hs + (size_t)s * I_ + base + 2 * tq) = __floats2half2_rn(r0v, r1v);
            }
        }
}

// ---- routed stage 2: out += g_hs @ W3[e] (atomic scatter) ----
__global__ __launch_bounds__(256, 2) void moe_routed_out_kernel(float* __restrict__ out)
{
    const int e = blockIdx.z;
    const int cnt = g_cnt[e];
    const int mb = blockIdx.y * BM;
    if (mb >= cnt) return;
    const int nb = blockIdx.x * BN;

    extern __shared__ __align__(16) char dsm[];
    const unsigned smb = (unsigned)__cvta_generic_to_shared(dsm);
    int* slotS = (int*)(dsm + 30720);
    const int tid = threadIdx.x;

    if (tid < BM) {
        int m = mb + tid;
        slotS[tid] = (m < cnt) ? g_slots[e * T_ + m] : g_slots[e * T_];
    }
    __syncthreads();

    const int am = tid >> 2, ac = tid & 3;
    const int bn = tid >> 1, bh = tid & 1;

    const __half* aRow = g_hs + (size_t)slotS[am] * I_;
    const __half* Bg   = g_w3h + (size_t)e * D_ * I_ + (size_t)nb * I_;
    const unsigned aD = smb + am * 80 + ac * 16;
    const unsigned bD = smb + 10240 + bn * 80 + bh * 32;

    WARP_IDS;

    float c[2][4][4] = {};

    #pragma unroll
    for (int s = 0; s < 2; s++) {
        A_COPY(aD + s * AB, aRow, s * BK);
        B_COPY(bD + s * BB, Bg, I_, s * BK);
        CP_COMMIT;
    }

    const int NT = I_ / BK;
    #pragma unroll 1
    for (int kt = 0; kt < NT; kt++) {
        const int s = kt & 1;
        if (kt + 1 < NT) CP_WAIT1; else CP_WAIT0;
        __syncthreads();
        const unsigned* Ar = (const unsigned*)dsm + s * AWRD;
        const unsigned* Br = (const unsigned*)dsm + 2560 + s * BWRD;
        #pragma unroll
        for (int ks = 0; ks < 2; ks++) {
            const int kq = ks * 8 + tq;
            LOAD_AFRAGS(Ar);
            #pragma unroll
            for (int in = 0; in < 4; in++) {
                int nc = nbase + in * 8 + grp;
                unsigned p0 = Br[nc * RSTR + kq], p1 = Br[nc * RSTR + kq + 4];
                MMA16(c[0][in], a0, p0, p1);
                MMA16(c[1][in], a1, p0, p1);
            }
        }
        if (kt + 2 < NT) {
            __syncthreads();
            const int k0 = (kt + 2) * BK;
            A_COPY(aD + s * AB, aRow, k0);
            B_COPY(bD + s * BB, Bg, I_, k0);
            CP_COMMIT;
        }
    }

    #pragma unroll
    for (int im = 0; im < 2; im++)
        #pragma unroll
        for (int h = 0; h < 2; h++) {
            int lr = mbase + im * 16 + grp + h * 8;
            if ((mb + lr) < cnt) {
                int t = slotS[lr] / K_;
                #pragma unroll
                for (int in = 0; in < 4; in++)
                    #pragma unroll
                    for (int q2 = 0; q2 < 2; q2++) {
                        int col = nb + nbase + in * 8 + 2 * tq + q2;
                        atomicAdd(&out[(size_t)t * D_ + col], c[im][in][h * 2 + q2]);
                    }
            }
        }
}

// ---------------- static init: dynamic-smem opt-in ----------------
namespace {
struct MoeInit {
    MoeInit() {
        cudaFuncSetAttribute(moe_shared_h_kernel,   cudaFuncAttributeMaxDynamicSharedMemorySize, DUAL_SMEM);
        cudaFuncSetAttribute(moe_routed_h_kernel,   cudaFuncAttributeMaxDynamicSharedMemorySize, DUAL_SMEM);
        cudaFuncSetAttribute(moe_out_init_kernel,   cudaFuncAttributeMaxDynamicSharedMemorySize, SINGLE_SMEM);
        cudaFuncSetAttribute(moe_routed_out_kernel, cudaFuncAttributeMaxDynamicSharedMemorySize, SINGLE_SMEM);
    }
};
MoeInit g_moe_init;
}

// ---------------- launch (single stream) ----------------
extern "C" void kernel_launch(void* const* d_in, const int* in_sizes, int n_in,
                              void* d_out, int out_size)
{
    (void)in_sizes; (void)n_in; (void)out_size;
    const float* x   = (const float*)d_in[0];
    const float* rw  = (const float*)d_in[1];
    const float* rb  = (const float*)d_in[2];
    const float* W1  = (const float*)d_in[3];
    const float* b1  = (const float*)d_in[4];
    const float* W2  = (const float*)d_in[5];
    const float* b2  = (const float*)d_in[6];
    const float* W3  = (const float*)d_in[7];
    const float* b3  = (const float*)d_in[8];
    const float* sw1 = (const float*)d_in[9];
    const float* sb1 = (const float*)d_in[10];
    const float* sw2 = (const float*)d_in[11];
    const float* sb2 = (const float*)d_in[12];
    const float* sw3 = (const float*)d_in[13];
    const float* sb3 = (const float*)d_in[14];
    float* out = (float*)d_out;

    dim3 tb(32, 8);
    moe_init_kernel<<<1, 32>>>();
    moe_tr_kernel<<<dim3(I_ / 32, D_ / 32, E_), tb>>>(W1, 0, D_, I_);
    moe_tr_kernel<<<dim3(I_ / 32, D_ / 32, E_), tb>>>(W2, 1, D_, I_);
    moe_tr_kernel<<<dim3(D_ / 32, I_ / 32, E_), tb>>>(W3, 2, I_, D_);
    moe_tr_kernel<<<dim3(SI_ / 32, D_ / 32, 1), tb>>>(sw1, 3, D_, SI_);
    moe_tr_kernel<<<dim3(SI_ / 32, D_ / 32, 1), tb>>>(sw2, 4, D_, SI_);
    moe_tr_kernel<<<dim3(D_ / 32, SI_ / 32, 1), tb>>>(sw3, 5, SI_, D_);
    moe_cvtx_kernel<<<T_ * D_ / 4 / 256, 256>>>(x);
    moe_router_kernel<<<T_ / 8, 256>>>(x, rw, rb);
    moe_bias_kernel<<<T_, 256>>>(b3, sb3, out);
    moe_shared_h_kernel<<<dim3(SI_ / BN, T_ / BM), 256, DUAL_SMEM>>>(sb1, sb2);
    moe_out_init_kernel<<<dim3(D_ / BN, T_ / BM), 256, SINGLE_SMEM>>>(out);
    moe_routed_h_kernel<<<dim3(I_ / BN, T_ / BM, E_), 256, DUAL_SMEM>>>(b1, b2);
    moe_routed_out_kernel<<<dim3(D_ / BN, T_ / BM, E_), 256, SINGLE_SMEM>>>(out);
}

// round 16
// speedup vs baseline: 1.9543x; 1.9543x over previous
#include <cuda_runtime.h>
#include <cuda_fp16.h>
#include <math.h>
#include <stdint.h>

#define T_  2048
#define D_  1024
#define I_  512
#define E_  32
#define K_  6
#define SI_ 1024

#define BM 64
#define BN 128
#define BK 32
#define ASTR 20      // A smem row stride (words): 16 data + 4 pad, conflict-free
#define BSTR 136     // B smem k-pair row stride (words): R7-proven conflict-free
#define AWRD (BM * ASTR)          // 1280 words per A stage
#define BWRD (16 * BSTR)          // 2176 words per B stage (16 k-pair rows)
#define AB (AWRD * 4)             // 5120 B
#define BB (BWRD * 4)             // 8704 B

// word offsets: A[2]@0 (2560), B1[2]@2560 (4352), B2[2]@6912 (4352)
#define B1OFF 2560
#define B2OFF 6912
#define DUAL_SLOTB   (11264 * 4)   // 45056 B
#define SINGLE_SLOTB (6912 * 4)    // 27648 B
#define DUAL_SMEM   (DUAL_SLOTB + 256)
#define SINGLE_SMEM (SINGLE_SLOTB + 256)

// ---------------- scratch (no allocations allowed) ----------------
// weights packed as k-pair half2 words: [k/2][n], word = (w[2kp][n], w[2kp+1][n])
__device__ __half g_w1h[E_ * D_ * I_];
__device__ __half g_w2h[E_ * D_ * I_];
__device__ __half g_w3h[E_ * I_ * D_];
__device__ __half g_sw1h[D_ * SI_];
__device__ __half g_sw2h[D_ * SI_];
__device__ __half g_sw3h[SI_ * D_];
__device__ __half g_xh[T_ * D_];         // x fp16 (k-contiguous rows)
__device__ __half g_zh[T_ * SI_];        // shared hidden fp16
__device__ __half g_hs[T_ * K_ * I_];    // routed hidden fp16
__device__ int    g_cnt[E_];
__device__ int    g_slots[E_ * T_];
__device__ int    g_tidx[T_ * K_];
__device__ float  g_tval[T_ * K_];

__device__ __forceinline__ void cpa16(unsigned dst, const void* src) {
    asm volatile("cp.async.cg.shared.global [%0], [%1], 16;" :: "r"(dst), "l"(src));
}
#define CP_COMMIT asm volatile("cp.async.commit_group;")
#define CP_WAIT1  asm volatile("cp.async.wait_group 1;")
#define CP_WAIT0  asm volatile("cp.async.wait_group 0;")

#define MMA16(c, a, b0v, b1v) \
    asm volatile("mma.sync.aligned.m16n8k16.row.col.f32.f16.f16.f32 " \
        "{%0,%1,%2,%3},{%4,%5,%6,%7},{%8,%9},{%0,%1,%2,%3};" \
        : "+f"((c)[0]), "+f"((c)[1]), "+f"((c)[2]), "+f"((c)[3]) \
        : "r"((a)[0]), "r"((a)[1]), "r"((a)[2]), "r"((a)[3]), "r"(b0v), "r"(b1v))

// ---------------- init ----------------
__global__ void moe_init_kernel() {
    if (threadIdx.x < E_) g_cnt[threadIdx.x] = 0;
}

// ---------------- k-pair pack: src f32 [ROWS][C] -> dst half2-words [ROWS/2][C] ----------------
// dst resolved in DEVICE code (R9/R13 lesson: host-side __device__ symbol args are poison).
__device__ __forceinline__ __half2* pk_dst(int which) {
    switch (which) {
        case 0: return (__half2*)g_w1h;
        case 1: return (__half2*)g_w2h;
        case 2: return (__half2*)g_w3h;
        case 3: return (__half2*)g_sw1h;
        case 4: return (__half2*)g_sw2h;
        default: return (__half2*)g_sw3h;
    }
}

__global__ __launch_bounds__(256) void moe_pack_kernel(
    const float* __restrict__ src, int which, int C)
{
    __half2* dst = pk_dst(which);
    long idx = (long)blockIdx.x * 256 + threadIdx.x;   // one thread = 4 words (4 n-cols)
    long w4 = idx * 4;
    long kp = w4 / C;
    int  n  = (int)(w4 % C);
    const float4 a = *(const float4*)(src + (2 * kp) * C + n);
    const float4 b = *(const float4*)(src + (2 * kp + 1) * C + n);
    dst[w4 + 0] = __floats2half2_rn(a.x, b.x);
    dst[w4 + 1] = __floats2half2_rn(a.y, b.y);
    dst[w4 + 2] = __floats2half2_rn(a.z, b.z);
    dst[w4 + 3] = __floats2half2_rn(a.w, b.w);
}

// ---------------- x -> fp16 (k-contiguous rows) ----------------
__global__ __launch_bounds__(256) void moe_cvtx_kernel(const float* __restrict__ x) {
    long i = (long)blockIdx.x * 256 + threadIdx.x;
    float4 v = ((const float4*)x)[i];
    ((__half2*)g_xh)[i * 2]     = __floats2half2_rn(v.x, v.y);
    ((__half2*)g_xh)[i * 2 + 1] = __floats2half2_rn(v.z, v.w);
}

// ---------------- router: 1 warp per token (validated, fp32) ----------------
__global__ __launch_bounds__(256) void moe_router_kernel(
    const float* __restrict__ x, const float* __restrict__ rw, const float* __restrict__ rb)
{
    __shared__ float sh[8][32];
    const int wi = threadIdx.x >> 5, lane = threadIdx.x & 31;
    const int t = blockIdx.x * 8 + wi;

    const float4* xr = (const float4*)(x + (size_t)t * D_);
    float4 xv[8];
    #pragma unroll
    for (int d = 0; d < 8; d++) xv[d] = xr[d * 32 + lane];

    for (int e = 0; e < E_; e += 2) {
        const float4* w0 = (const float4*)(rw + (size_t)e * D_);
        const float4* w1 = (const float4*)(rw + (size_t)(e + 1) * D_);
        float acc0 = 0.f, acc1 = 0.f;
        #pragma unroll
        for (int d = 0; d < 8; d++) {
            float4 b0 = w0[d * 32 + lane], b1 = w1[d * 32 + lane];
            acc0 += xv[d].x * b0.x + xv[d].y * b0.y + xv[d].z * b0.z + xv[d].w * b0.w;
            acc1 += xv[d].x * b1.x + xv[d].y * b1.y + xv[d].z * b1.z + xv[d].w * b1.w;
        }
        #pragma unroll
        for (int off = 16; off; off >>= 1) {
            acc0 += __shfl_down_sync(0xffffffffu, acc0, off);
            acc1 += __shfl_down_sync(0xffffffffu, acc1, off);
        }
        if (lane == 0) { sh[wi][e] = acc0 + rb[e]; sh[wi][e + 1] = acc1 + rb[e + 1]; }
    }
    __syncwarp();
    float logit = sh[wi][lane];

    float mx = logit;
    #pragma unroll
    for (int off = 16; off; off >>= 1)
        mx = fmaxf(mx, __shfl_xor_sync(0xffffffffu, mx, off));
    float p = expf(logit - mx);
    float sm = p;
    #pragma unroll
    for (int off = 16; off; off >>= 1)
        sm += __shfl_xor_sync(0xffffffffu, sm, off);
    float score = p / sm;

    const int grp = lane >> 2;
    float v0 = __shfl_sync(0xffffffffu, score, grp * 4 + 0);
    float v1 = __shfl_sync(0xffffffffu, score, grp * 4 + 1);
    float v2 = __shfl_sync(0xffffffffu, score, grp * 4 + 2);
    float v3 = __shfl_sync(0xffffffffu, score, grp * 4 + 3);
    float a = fmaxf(v0, v1), b = fminf(v0, v1);
    float c = fmaxf(v2, v3), dd = fminf(v2, v3);
    float top2 = (a >= c) ? (a + fmaxf(b, c)) : (c + fmaxf(a, dd));

    float gsa[8];
    #pragma unroll
    for (int j = 0; j < 8; j++) gsa[j] = __shfl_sync(0xffffffffu, top2, j * 4);
    unsigned keep = 0;
    #pragma unroll
    for (int it = 0; it < 4; it++) {
        float bv = -1e30f; int bj = 0;
        #pragma unroll
        for (int j = 0; j < 8; j++) {
            bool cand = (((keep >> j) & 1u) == 0u) && (gsa[j] > bv);
            if (cand) { bv = gsa[j]; bj = j; }
        }
        keep |= 1u << bj;
    }

    float msc = ((keep >> grp) & 1u) ? score : -1e30f;
    __syncwarp();
    sh[wi][lane] = msc;
    __syncwarp();

    if (lane == 0) {
        #pragma unroll
        for (int kk = 0; kk < K_; kk++) {
            float bv = -1e30f; int be = 0;
            for (int ee = 0; ee < 32; ee++) {
                float s = sh[wi][ee];
                if (s > bv) { bv = s; be = ee; }
            }
            sh[wi][be] = -2e30f;
            g_tidx[t * K_ + kk] = be;
            g_tval[t * K_ + kk] = bv;
            int pos = atomicAdd(&g_cnt[be], 1);
            g_slots[be * T_ + pos] = t * K_ + kk;
        }
    }
}

// ---------------- bias pre-pass: out[t] = sb3 + sum_k gate_k * b3[e_k] ----------------
__global__ __launch_bounds__(256) void moe_bias_kernel(
    const float* __restrict__ b3, const float* __restrict__ sb3, float* __restrict__ out)
{
    const int t = blockIdx.x;
    int ti[K_]; float tv[K_];
    #pragma unroll
    for (int k = 0; k < K_; k++) { ti[k] = g_tidx[t * K_ + k]; tv[k] = g_tval[t * K_ + k]; }
    for (int n = threadIdx.x * 4; n < D_; n += blockDim.x * 4) {
        float4 v = *(const float4*)(sb3 + n);
        #pragma unroll
        for (int k = 0; k < K_; k++) {
            float4 bb = *(const float4*)(b3 + (size_t)ti[k] * D_ + n);
            v.x = fmaf(tv[k], bb.x, v.x); v.y = fmaf(tv[k], bb.y, v.y);
            v.z = fmaf(tv[k], bb.z, v.z); v.w = fmaf(tv[k], bb.w, v.w);
        }
        *(float4*)(out + (size_t)t * D_ + n) = v;
    }
}

// ======================================================================
// fp16 m16n8k16 GEMMs, k-pair-major B. R7 skeleton: 256 thr, 8 warps (2x4),
// warp 32x32, BK=32 (2 k16-slices), 2-stage pipeline.
// A smem: [m][k halfs], 20-word rows. B smem: [kp][n words], 136-word rows.
// ======================================================================

// A: thread t -> row am=t>>2, chunk ac=t&3 (16B = 8 halfs)
#define A_COPY(dstbase, rowptr, k0)  cpa16((dstbase), (rowptr) + (k0) + ac * 8)
// B: thread t -> kp-row bkp=t>>4, chunks bc=(t&15) and bc+16 (ldn in words; gbase = uint*)
#define B_COPY(dstbase, gbase, ldn, k0) do { \
    cpa16((dstbase),       (gbase) + (size_t)((k0) / 2 + bkp) * (ldn) + bc * 4); \
    cpa16((dstbase) + 256,  (gbase) + (size_t)((k0) / 2 + bkp) * (ldn) + bc * 4 + 64); \
} while (0)

#define WARP_IDS \
    const int lane = tid & 31, warp = tid >> 5; \
    const int wm = warp >> 2, wn = warp & 3; \
    const int grp = lane >> 2, tq = lane & 3; \
    const int mbase = wm * 32, nbase = wn * 32;

#define LOAD_AFRAGS(Ar) \
    unsigned a0[4], a1[4]; \
    { int r0 = mbase + grp; \
      a0[0] = (Ar)[r0 * ASTR + kq];     a0[1] = (Ar)[(r0 + 8) * ASTR + kq]; \
      a0[2] = (Ar)[r0 * ASTR + kq + 4]; a0[3] = (Ar)[(r0 + 8) * ASTR + kq + 4]; \
      int r1 = r0 + 16; \
      a1[0] = (Ar)[r1 * ASTR + kq];     a1[1] = (Ar)[(r1 + 8) * ASTR + kq]; \
      a1[2] = (Ar)[r1 * ASTR + kq + 4]; a1[3] = (Ar)[(r1 + 8) * ASTR + kq + 4]; }

// ---- shared stage 1 (dual B): g_zh = fp16(silu((x@sw1+sb1)*(x@sw2+sb2))) ----
__global__ __launch_bounds__(256, 2) void moe_shared_h_kernel(
    const float* __restrict__ sb1, const float* __restrict__ sb2)
{
    extern __shared__ __align__(16) char dsm[];
    const unsigned smb = (unsigned)__cvta_generic_to_shared(dsm);
    const int tid = threadIdx.x;
    const int mb = blockIdx.y * BM, nb = blockIdx.x * BN;
    const int am = tid >> 2, ac = tid & 3;
    const int bkp = tid >> 4, bc = tid & 15;

    const __half* aRow = g_xh + (size_t)(mb + am) * D_;
    const unsigned* B1g = (const unsigned*)g_sw1h + nb;
    const unsigned* B2g = (const unsigned*)g_sw2h + nb;
    const unsigned aD  = smb + am * 80 + ac * 16;
    const unsigned b1D = smb + B1OFF * 4 + bkp * 544 + bc * 16;
    const unsigned b2D = smb + B2OFF * 4 + bkp * 544 + bc * 16;

    WARP_IDS;

    float c1[2][4][4] = {}, c2[2][4][4] = {};

    #pragma unroll
    for (int s = 0; s < 2; s++) {
        A_COPY(aD + s * AB, aRow, s * BK);
        B_COPY(b1D + s * BB, B1g, SI_, s * BK);
        B_COPY(b2D + s * BB, B2g, SI_, s * BK);
        CP_COMMIT;
    }

    const int NT = D_ / BK;
    #pragma unroll 1
    for (int kt = 0; kt < NT; kt++) {
        const int s = kt & 1;
        if (kt + 1 < NT) CP_WAIT1; else CP_WAIT0;
        __syncthreads();
        const unsigned* Ar  = (const unsigned*)dsm + s * AWRD;
        const unsigned* B1r = (const unsigned*)dsm + B1OFF + s * BWRD;
        const unsigned* B2r = (const unsigned*)dsm + B2OFF + s * BWRD;
        #pragma unroll
        for (int ks = 0; ks < 2; ks++) {
            const int kq = ks * 8 + tq;
            LOAD_AFRAGS(Ar);
            #pragma unroll
            for (int in = 0; in < 4; in++) {
                int nc = nbase + in * 8 + grp;
                unsigned p0 = B1r[kq * BSTR + nc], p1 = B1r[(kq + 4) * BSTR + nc];
                unsigned q0 = B2r[kq * BSTR + nc], q1 = B2r[(kq + 4) * BSTR + nc];
                MMA16(c1[0][in], a0, p0, p1);
                MMA16(c1[1][in], a1, p0, p1);
                MMA16(c2[0][in], a0, q0, q1);
                MMA16(c2[1][in], a1, q0, q1);
            }
        }
        if (kt + 2 < NT) {
            __syncthreads();
            const int k0 = (kt + 2) * BK;
            A_COPY(aD + s * AB, aRow, k0);
            B_COPY(b1D + s * BB, B1g, SI_, k0);
            B_COPY(b2D + s * BB, B2g, SI_, k0);
            CP_COMMIT;
        }
    }

    #pragma unroll
    for (int im = 0; im < 2; im++)
        #pragma unroll
        for (int in = 0; in < 4; in++)
            #pragma unroll
            for (int h = 0; h < 2; h++) {
                int row = mb + mbase + im * 16 + grp + h * 8;
                int base = nb + nbase + in * 8;
                float r0v, r1v;
                {
                    float h1 = c1[im][in][h * 2]     + sb1[base + 2 * tq];
                    float h2 = c2[im][in][h * 2]     + sb2[base + 2 * tq];
                    float pp = h1 * h2;
                    r0v = pp / (1.f + expf(-pp));
                }
                {
                    float h1 = c1[im][in][h * 2 + 1] + sb1[base + 2 * tq + 1];
                    float h2 = c2[im][in][h * 2 + 1] + sb2[base + 2 * tq + 1];
                    float pp = h1 * h2;
                    r1v = pp / (1.f + expf(-pp));
                }
                *(__half2*)(g_zh + (size_t)row * SI_ + base + 2 * tq) = __floats2half2_rn(r0v, r1v);
            }
}

// ---- shared stage 2: out += g_zh @ sw3 ----
__global__ __launch_bounds__(256, 2) void moe_out_init_kernel(float* __restrict__ out)
{
    extern __shared__ __align__(16) char dsm[];
    const unsigned smb = (unsigned)__cvta_generic_to_shared(dsm);
    const int tid = threadIdx.x;
    const int mb = blockIdx.y * BM, nb = blockIdx.x * BN;
    const int am = tid >> 2, ac = tid & 3;
    const int bkp = tid >> 4, bc = tid & 15;

    const __half* aRow = g_zh + (size_t)(mb + am) * SI_;
    const unsigned* Bg = (const unsigned*)g_sw3h + nb;
    const unsigned aD = smb + am * 80 + ac * 16;
    const unsigned bD = smb + B1OFF * 4 + bkp * 544 + bc * 16;

    WARP_IDS;

    float c[2][4][4] = {};

    #pragma unroll
    for (int s = 0; s < 2; s++) {
        A_COPY(aD + s * AB, aRow, s * BK);
        B_COPY(bD + s * BB, Bg, D_, s * BK);
        CP_COMMIT;
    }

    const int NT = SI_ / BK;
    #pragma unroll 1
    for (int kt = 0; kt < NT; kt++) {
        const int s = kt & 1;
        if (kt + 1 < NT) CP_WAIT1; else CP_WAIT0;
        __syncthreads();
        const unsigned* Ar = (const unsigned*)dsm + s * AWRD;
        const unsigned* Br = (const unsigned*)dsm + B1OFF + s * BWRD;
        #pragma unroll
        for (int ks = 0; ks < 2; ks++) {
            const int kq = ks * 8 + tq;
            LOAD_AFRAGS(Ar);
            #pragma unroll
            for (int in = 0; in < 4; in++) {
                int nc = nbase + in * 8 + grp;
                unsigned p0 = Br[kq * BSTR + nc], p1 = Br[(kq + 4) * BSTR + nc];
                MMA16(c[0][in], a0, p0, p1);
                MMA16(c[1][in], a1, p0, p1);
            }
        }
        if (kt + 2 < NT) {
            __syncthreads();
            const int k0 = (kt + 2) * BK;
            A_COPY(aD + s * AB, aRow, k0);
            B_COPY(bD + s * BB, Bg, D_, k0);
            CP_COMMIT;
        }
    }

    #pragma unroll
    for (int im = 0; im < 2; im++)
        #pragma unroll
        for (int in = 0; in < 4; in++)
            #pragma unroll
            for (int r = 0; r < 4; r++) {
                int row = mb + mbase + im * 16 + grp + (r >= 2 ? 8 : 0);
                int col = nb + nbase + in * 8 + 2 * tq + (r & 1);
                out[(size_t)row * D_ + col] += c[im][in][r];
            }
}

// ---- routed stage 1 (dual B, gathered rows) ----
__global__ __launch_bounds__(256, 2) void moe_routed_h_kernel(
    const float* __restrict__ b1, const float* __restrict__ b2)
{
    const int e = blockIdx.z;
    const int cnt = g_cnt[e];
    const int mb = blockIdx.y * BM;
    if (mb >= cnt) return;
    const int nb = blockIdx.x * BN;

    extern __shared__ __align__(16) char dsm[];
    const unsigned smb = (unsigned)__cvta_generic_to_shared(dsm);
    int* slotS = (int*)(dsm + DUAL_SLOTB);
    const int tid = threadIdx.x;

    if (tid < BM) {
        int m = mb + tid;
        slotS[tid] = (m < cnt) ? g_slots[e * T_ + m] : g_slots[e * T_];
    }
    __syncthreads();

    const int am = tid >> 2, ac = tid & 3;
    const int bkp = tid >> 4, bc = tid & 15;

    const __half* aRow = g_xh + (size_t)(slotS[am] / K_) * D_;
    const unsigned* B1g = (const unsigned*)g_w1h + (size_t)e * (D_ / 2) * I_ + nb;
    const unsigned* B2g = (const unsigned*)g_w2h + (size_t)e * (D_ / 2) * I_ + nb;
    const unsigned aD  = smb + am * 80 + ac * 16;
    const unsigned b1D = smb + B1OFF * 4 + bkp * 544 + bc * 16;
    const unsigned b2D = smb + B2OFF * 4 + bkp * 544 + bc * 16;

    WARP_IDS;

    float c1[2][4][4] = {}, c2[2][4][4] = {};

    #pragma unroll
    for (int s = 0; s < 2; s++) {
        A_COPY(aD + s * AB, aRow, s * BK);
        B_COPY(b1D + s * BB, B1g, I_, s * BK);
        B_COPY(b2D + s * BB, B2g, I_, s * BK);
        CP_COMMIT;
    }

    const int NT = D_ / BK;
    #pragma unroll 1
    for (int kt = 0; kt < NT; kt++) {
        const int s = kt & 1;
        if (kt + 1 < NT) CP_WAIT1; else CP_WAIT0;
        __syncthreads();
        const unsigned* Ar  = (const unsigned*)dsm + s * AWRD;
        const unsigned* B1r = (const unsigned*)dsm + B1OFF + s * BWRD;
        const unsigned* B2r = (const unsigned*)dsm + B2OFF + s * BWRD;
        #pragma unroll
        for (int ks = 0; ks < 2; ks++) {
            const int kq = ks * 8 + tq;
            LOAD_AFRAGS(Ar);
            #pragma unroll
            for (int in = 0; in < 4; in++) {
                int nc = nbase + in * 8 + grp;
                unsigned p0 = B1r[kq * BSTR + nc], p1 = B1r[(kq + 4) * BSTR + nc];
                unsigned q0 = B2r[kq * BSTR + nc], q1 = B2r[(kq + 4) * BSTR + nc];
                MMA16(c1[0][in], a0, p0, p1);
                MMA16(c1[1][in], a1, p0, p1);
                MMA16(c2[0][in], a0, q0, q1);
                MMA16(c2[1][in], a1, q0, q1);
            }
        }
        if (kt + 2 < NT) {
            __syncthreads();
            const int k0 = (kt + 2) * BK;
            A_COPY(aD + s * AB, aRow, k0);
            B_COPY(b1D + s * BB, B1g, I_, k0);
            B_COPY(b2D + s * BB, B2g, I_, k0);
            CP_COMMIT;
        }
    }

    #pragma unroll
    for (int im = 0; im < 2; im++)
        #pragma unroll
        for (int h = 0; h < 2; h++) {
            int lr = mbase + im * 16 + grp + h * 8;
            bool valid = (mb + lr) < cnt;
            int s = slotS[lr];
            float gv = g_tval[s];
            #pragma unroll
            for (int in = 0; in < 4; in++) {
                int base = nb + nbase + in * 8;
                float r0v, r1v;
                {
                    float h1 = c1[im][in][h * 2]     + b1[(size_t)e * I_ + base + 2 * tq];
                    float h2 = c2[im][in][h * 2]     + b2[(size_t)e * I_ + base + 2 * tq];
                    float pp = h1 * h2;
                    r0v = gv * pp / (1.f + expf(-pp));
                }
                {
                    float h1 = c1[im][in][h * 2 + 1] + b1[(size_t)e * I_ + base + 2 * tq + 1];
                    float h2 = c2[im][in][h * 2 + 1] + b2[(size_t)e * I_ + base + 2 * tq + 1];
                    float pp = h1 * h2;
                    r1v = gv * pp / (1.f + expf(-pp));
                }
                if (valid)
                    *(__half2*)(g_hs + (size_t)s * I_ + base + 2 * tq) = __floats2half2_rn(r0v, r1v);
            }
        }
}

// ---- routed stage 2: out += g_hs @ W3[e] (atomic scatter) ----
__global__ __launch_bounds__(256, 2) void moe_routed_out_kernel(float* __restrict__ out)
{
    const int e = blockIdx.z;
    const int cnt = g_cnt[e];
    const int mb = blockIdx.y * BM;
    if (mb >= cnt) return;
    const int nb = blockIdx.x * BN;

    extern __shared__ __align__(16) char dsm[];
    const unsigned smb = (unsigned)__cvta_generic_to_shared(dsm);
    int* slotS = (int*)(dsm + SINGLE_SLOTB);
    const int tid = threadIdx.x;

    if (tid < BM) {
        int m = mb + tid;
        slotS[tid] = (m < cnt) ? g_slots[e * T_ + m] : g_slots[e * T_];
    }
    __syncthreads();

    const int am = tid >> 2, ac = tid & 3;
    const int bkp = tid >> 4, bc = tid & 15;

    const __half* aRow = g_hs + (size_t)slotS[am] * I_;
    const unsigned* Bg = (const unsigned*)g_w3h + (size_t)e * (I_ / 2) * D_ + nb;
    const unsigned aD = smb + am * 80 + ac * 16;
    const unsigned bD = smb + B1OFF * 4 + bkp * 544 + bc * 16;

    WARP_IDS;

    float c[2][4][4] = {};

    #pragma unroll
    for (int s = 0; s < 2; s++) {
        A_COPY(aD + s * AB, aRow, s * BK);
        B_COPY(bD + s * BB, Bg, D_, s * BK);
        CP_COMMIT;
    }

    const int NT = I_ / BK;
    #pragma unroll 1
    for (int kt = 0; kt < NT; kt++) {
        const int s = kt & 1;
        if (kt + 1 < NT) CP_WAIT1; else CP_WAIT0;
        __syncthreads();
        const unsigned* Ar = (const unsigned*)dsm + s * AWRD;
        const unsigned* Br = (const unsigned*)dsm + B1OFF + s * BWRD;
        #pragma unroll
        for (int ks = 0; ks < 2; ks++) {
            const int kq = ks * 8 + tq;
            LOAD_AFRAGS(Ar);
            #pragma unroll
            for (int in = 0; in < 4; in++) {
                int nc = nbase + in * 8 + grp;
                unsigned p0 = Br[kq * BSTR + nc], p1 = Br[(kq + 4) * BSTR + nc];
                MMA16(c[0][in], a0, p0, p1);
                MMA16(c[1][in], a1, p0, p1);
            }
        }
        if (kt + 2 < NT) {
            __syncthreads();
            const int k0 = (kt + 2) * BK;
            A_COPY(aD + s * AB, aRow, k0);
            B_COPY(bD + s * BB, Bg, D_, k0);
            CP_COMMIT;
        }
    }

    #pragma unroll
    for (int im = 0; im < 2; im++)
        #pragma unroll
        for (int h = 0; h < 2; h++) {
            int lr = mbase + im * 16 + grp + h * 8;
            if ((mb + lr) < cnt) {
                int t = slotS[lr] / K_;
                #pragma unroll
                for (int in = 0; in < 4; in++)
                    #pragma unroll
                    for (int q2 = 0; q2 < 2; q2++) {
                        int col = nb + nbase + in * 8 + 2 * tq + q2;
                        atomicAdd(&out[(size_t)t * D_ + col], c[im][in][h * 2 + q2]);
                    }
            }
        }
}

// ---------------- static init: dynamic-smem opt-in ----------------
namespace {
struct MoeInit {
    MoeInit() {
        cudaFuncSetAttribute(moe_shared_h_kernel,   cudaFuncAttributeMaxDynamicSharedMemorySize, DUAL_SMEM);
        cudaFuncSetAttribute(moe_routed_h_kernel,   cudaFuncAttributeMaxDynamicSharedMemorySize, DUAL_SMEM);
        cudaFuncSetAttribute(moe_out_init_kernel,   cudaFuncAttributeMaxDynamicSharedMemorySize, SINGLE_SMEM);
        cudaFuncSetAttribute(moe_routed_out_kernel, cudaFuncAttributeMaxDynamicSharedMemorySize, SINGLE_SMEM);
    }
};
MoeInit g_moe_init;
}

// ---------------- launch (single stream) ----------------
extern "C" void kernel_launch(void* const* d_in, const int* in_sizes, int n_in,
                              void* d_out, int out_size)
{
    (void)in_sizes; (void)n_in; (void)out_size;
    const float* x   = (const float*)d_in[0];
    const float* rw  = (const float*)d_in[1];
    const float* rb  = (const float*)d_in[2];
    const float* W1  = (const float*)d_in[3];
    const float* b1  = (const float*)d_in[4];
    const float* W2  = (const float*)d_in[5];
    const float* b2  = (const float*)d_in[6];
    const float* W3  = (const float*)d_in[7];
    const float* b3  = (const float*)d_in[8];
    const float* sw1 = (const float*)d_in[9];
    const float* sb1 = (const float*)d_in[10];
    const float* sw2 = (const float*)d_in[11];
    const float* sb2 = (const float*)d_in[12];
    const float* sw3 = (const float*)d_in[13];
    const float* sb3 = (const float*)d_in[14];
    float* out = (float*)d_out;

    const int GW = E_ * D_ * I_ / 2 / 4 / 256;   // 8192  (W1/W2/W3)
    const int GS = D_ * SI_ / 2 / 4 / 256;       // 512   (sw1/sw2/sw3)
    moe_init_kernel<<<1, 32>>>();
    moe_pack_kernel<<<GW, 256>>>(W1, 0, I_);
    moe_pack_kernel<<<GW, 256>>>(W2, 1, I_);
    moe_pack_kernel<<<GW, 256>>>(W3, 2, D_);
    moe_pack_kernel<<<GS, 256>>>(sw1, 3, SI_);
    moe_pack_kernel<<<GS, 256>>>(sw2, 4, SI_);
    moe_pack_kernel<<<GS, 256>>>(sw3, 5, D_);
    moe_cvtx_kernel<<<T_ * D_ / 4 / 256, 256>>>(x);
    moe_router_kernel<<<T_ / 8, 256>>>(x, rw, rb);
    moe_bias_kernel<<<T_, 256>>>(b3, sb3, out);
    moe_shared_h_kernel<<<dim3(SI_ / BN, T_ / BM), 256, DUAL_SMEM>>>(sb1, sb2);
    moe_out_init_kernel<<<dim3(D_ / BN, T_ / BM), 256, SINGLE_SMEM>>>(out);
    moe_routed_h_kernel<<<dim3(I_ / BN, T_ / BM, E_), 256, DUAL_SMEM>>>(b1, b2);
    moe_routed_out_kernel<<<dim3(D_ / BN, T_ / BM, E_), 256, SINGLE_SMEM>>>(out);
}